// round 4
// baseline (speedup 1.0000x reference)
#include <cuda_runtime.h>
#include <cstdint>

typedef unsigned long long ull;
typedef unsigned int u32;

#define L 512
#define H 1024
#define C 2

// Scratch
__device__ float g_ap[L * H];      // a_proj + b1, [l][o]
__device__ float g_bp[L * H];      // b_proj,      [l][o]
__device__ float g_f[L * L * C];   // unsymmetrized logits f[i][j][c]

// ---- packed f32x2 helpers ----
__device__ __forceinline__ ull ffma2(ull a, ull b, ull c) {
    ull d;
    asm("fma.rn.f32x2 %0, %1, %2, %3;" : "=l"(d) : "l"(a), "l"(b), "l"(c));
    return d;
}
__device__ __forceinline__ ull fadd2(ull a, ull b) {
    ull d;
    asm("add.rn.f32x2 %0, %1, %2;" : "=l"(d) : "l"(a), "l"(b));
    return d;
}
__device__ __forceinline__ float2 u2f2(ull u) {
    float2 v;
    asm("mov.b64 {%0, %1}, %2;" : "=f"(v.x), "=f"(v.y) : "l"(u));
    return v;
}
__device__ __forceinline__ ull tanh2(ull x) {
    ull r;
    asm("{\n\t"
        ".reg .f32 lo, hi;\n\t"
        "mov.b64 {lo, hi}, %1;\n\t"
        "tanh.approx.f32 lo, lo;\n\t"
        "tanh.approx.f32 hi, hi;\n\t"
        "mov.b64 %0, {lo, hi};\n\t"
        "}" : "=l"(r) : "l"(x));
    return r;
}
__device__ __forceinline__ u32 to_tf32(float f) {
    u32 r;
    asm("cvt.rna.tf32.f32 %0, %1;" : "=r"(r) : "f"(f));
    return r;
}
__device__ __forceinline__ void mma_tf32(float c[4], u32 a0, u32 a1, u32 a2, u32 a3,
                                         u32 b0, u32 b1) {
    asm("mma.sync.aligned.m16n8k8.row.col.f32.tf32.tf32.f32 "
        "{%0,%1,%2,%3}, {%4,%5,%6,%7}, {%8,%9}, {%0,%1,%2,%3};"
        : "+f"(c[0]), "+f"(c[1]), "+f"(c[2]), "+f"(c[3])
        : "r"(a0), "r"(a1), "r"(a2), "r"(a3), "r"(b0), "r"(b1));
}

// ============================================================
// Kernel 1: tf32 tensor GEMM, fragment-major smem + double buffer.
// CTA: 64 l x 64 o, computing BOTH ap and bp (shared A tile).
// 8 warps: warp grid 2(m) x 4(n); warp tile 32m x 16n x {ap,bp}.
// Fragments stored pre-permuted: A = uint4{a0..a3}/lane (LDS.128),
// B = uint2{b0,b1}/lane (LDS.64).
// ============================================================
#define G_BM 64
#define G_BN 64
#define G_KC 32

__global__ __launch_bounds__(256) void k1_mma(const float* __restrict__ x,
                                              const float* __restrict__ W1,
                                              const float* __restrict__ b1) {
    // [buf][kstep][mblock16][lane] = {a0,a1,a2,a3}
    __shared__ uint4 xs_f[2][4][4][32];
    // [buf][ab][kstep][nblock8][lane] = {b0,b1}
    __shared__ uint2 wf[2][2][4][8][32];

    const int t = threadIdx.x;
    const int lane = t & 31;
    const int wid = t >> 5;
    const int gid = lane >> 2;
    const int tig = lane & 3;
    const int wm = wid & 1;        // 2 m-warps (32 rows each)
    const int wn = wid >> 1;       // 4 n-warps (16 cols each)
    const int lblk = blockIdx.y * G_BM;
    const int oblk = blockIdx.x * G_BN;

    // loader mapping: rows r0 and r0+32, 4 consecutive k at k4
    const int r0 = t >> 3;              // 0..31
    const int k4 = (t & 7) * 4;         // 0..28
    const int a_ks = k4 >> 3;           // kstep
    const int sl_k = (k4 >> 2) & 1;     // k-half within fragment

    const float* xp0 = x + (lblk + r0) * H + k4;
    const float* xp1 = x + (lblk + r0 + 32) * H + k4;
    const float* wp0 = W1 + (oblk + r0) * (2 * H) + k4;
    const float* wp1 = W1 + (oblk + r0 + 32) * (2 * H) + k4;

    float accA[2][2][4], accB[2][2][4];
#pragma unroll
    for (int mi = 0; mi < 2; mi++)
#pragma unroll
        for (int na = 0; na < 2; na++)
#pragma unroll
            for (int q = 0; q < 4; q++) { accA[mi][na][q] = 0.f; accB[mi][na][q] = 0.f; }

    float4 rx[2], rwa[2], rwb[2];

#define LOAD_GLB(kb)                                        \
    do {                                                    \
        rx[0]  = *(const float4*)(xp0 + (kb));              \
        rx[1]  = *(const float4*)(xp1 + (kb));              \
        rwa[0] = *(const float4*)(wp0 + (kb));              \
        rwb[0] = *(const float4*)(wp0 + (kb) + H);          \
        rwa[1] = *(const float4*)(wp1 + (kb));              \
        rwb[1] = *(const float4*)(wp1 + (kb) + H);          \
    } while (0)

#define STORE_TILES(bf)                                                   \
    do {                                                                  \
        _Pragma("unroll")                                                 \
        for (int q = 0; q < 2; q++) {                                     \
            const int r = r0 + q * 32;                                    \
            /* A fragment store */                                        \
            const int mb = r >> 4;                                        \
            const int slA = ((r >> 3) & 1) + 2 * sl_k;                    \
            u32* ba = (u32*)&xs_f[bf][a_ks][mb][(r & 7) * 4];             \
            ba[0 * 4 + slA] = to_tf32(rx[q].x);                           \
            ba[1 * 4 + slA] = to_tf32(rx[q].y);                           \
            ba[2 * 4 + slA] = to_tf32(rx[q].z);                           \
            ba[3 * 4 + slA] = to_tf32(rx[q].w);                           \
            /* B fragment stores (ap half, bp half) */                    \
            const int nb8 = r >> 3;                                       \
            u32* bw0 = (u32*)&wf[bf][0][a_ks][nb8][(r & 7) * 4];          \
            bw0[0 * 2 + sl_k] = to_tf32(rwa[q].x);                        \
            bw0[1 * 2 + sl_k] = to_tf32(rwa[q].y);                        \
            bw0[2 * 2 + sl_k] = to_tf32(rwa[q].z);                        \
            bw0[3 * 2 + sl_k] = to_tf32(rwa[q].w);                        \
            u32* bw1 = (u32*)&wf[bf][1][a_ks][nb8][(r & 7) * 4];          \
            bw1[0 * 2 + sl_k] = to_tf32(rwb[q].x);                        \
            bw1[1 * 2 + sl_k] = to_tf32(rwb[q].y);                        \
            bw1[2 * 2 + sl_k] = to_tf32(rwb[q].z);                        \
            bw1[3 * 2 + sl_k] = to_tf32(rwb[q].w);                        \
        }                                                                 \
    } while (0)

#define COMPUTE(bf)                                                       \
    do {                                                                  \
        _Pragma("unroll")                                                 \
        for (int ks = 0; ks < 4; ks++) {                                  \
            uint4 A0 = xs_f[bf][ks][wm * 2 + 0][lane];                    \
            uint4 A1 = xs_f[bf][ks][wm * 2 + 1][lane];                    \
            _Pragma("unroll")                                             \
            for (int na = 0; na < 2; na++) {                              \
                uint2 Ba = wf[bf][0][ks][wn * 2 + na][lane];              \
                uint2 Bb = wf[bf][1][ks][wn * 2 + na][lane];              \
                mma_tf32(accA[0][na], A0.x, A0.y, A0.z, A0.w, Ba.x, Ba.y);\
                mma_tf32(accA[1][na], A1.x, A1.y, A1.z, A1.w, Ba.x, Ba.y);\
                mma_tf32(accB[0][na], A0.x, A0.y, A0.z, A0.w, Bb.x, Bb.y);\
                mma_tf32(accB[1][na], A1.x, A1.y, A1.z, A1.w, Bb.x, Bb.y);\
            }                                                             \
        }                                                                 \
    } while (0)

    LOAD_GLB(0);
    STORE_TILES(0);
    __syncthreads();

    int buf = 0;
#pragma unroll 4
    for (int it = 0; it < H / G_KC; it++) {
        if (it < H / G_KC - 1) LOAD_GLB((it + 1) * G_KC);
        COMPUTE(buf);
        if (it < H / G_KC - 1) {
            STORE_TILES(buf ^ 1);
            __syncthreads();
            buf ^= 1;
        }
    }

    // epilogue: c0=(g,2t) c1=(g,2t+1) c2=(g+8,2t) c3=(g+8,2t+1)
#pragma unroll
    for (int mi = 0; mi < 2; mi++) {
        const int row0 = lblk + wm * 32 + mi * 16 + gid;
#pragma unroll
        for (int na = 0; na < 2; na++) {
            const int col = oblk + wn * 16 + na * 8 + tig * 2;
            const float2 bv = *(const float2*)&b1[col];
            float2 v;
            v.x = accA[mi][na][0] + bv.x; v.y = accA[mi][na][1] + bv.y;
            *(float2*)&g_ap[row0 * H + col] = v;
            v.x = accA[mi][na][2] + bv.x; v.y = accA[mi][na][3] + bv.y;
            *(float2*)&g_ap[(row0 + 8) * H + col] = v;
            v.x = accB[mi][na][0]; v.y = accB[mi][na][1];
            *(float2*)&g_bp[row0 * H + col] = v;
            v.x = accB[mi][na][2]; v.y = accB[mi][na][3];
            *(float2*)&g_bp[(row0 + 8) * H + col] = v;
        }
    }
#undef LOAD_GLB
#undef STORE_TILES
#undef COMPUTE
}

// ============================================================
// Kernel 2: f[i,j,c] = sum_h tanh(ap[j,h] + bp[i,h]) * W2[c,h]
// Tile 16i x 32j, 256 threads (1i x 2j each), HC=128. MUFU-bound.
// ============================================================
#define P_TI 16
#define P_TJ 32
#define P_HC 128
#define P_PAD 130

__global__ __launch_bounds__(256) void k2_pair(const float* __restrict__ W2) {
    __shared__ __align__(16) float as[P_TJ][P_PAD];   // ap rows (j)
    __shared__ __align__(16) float bs[P_TI][P_PAD];   // bp rows (i)
    __shared__ __align__(16) float w2s[2][P_HC];

    const int t = threadIdx.x;
    const int tx = t & 15;   // j
    const int ty = t >> 4;   // i (16 values)
    const int jblk = blockIdx.x * P_TJ;
    const int iblk = blockIdx.y * P_TI;

    ull acc[2][2];   // [jv][c]
    acc[0][0] = acc[0][1] = acc[1][0] = acc[1][1] = 0ull;

    for (int hb = 0; hb < H; hb += P_HC) {
        // as: 32 x 128 floats = 2048 float2, 8/thread
#pragma unroll
        for (int q = 0; q < 8; q++) {
            int idx = t + q * 256;
            int r = idx >> 6, c = (idx & 63) * 2;
            *(float2*)&as[r][c] = *(const float2*)&g_ap[(jblk + r) * H + hb + c];
        }
        // bs: 16 x 128 = 1024 float2, 4/thread
#pragma unroll
        for (int q = 0; q < 4; q++) {
            int idx = t + q * 256;
            int r = idx >> 6, c = (idx & 63) * 2;
            *(float2*)&bs[r][c] = *(const float2*)&g_bp[(iblk + r) * H + hb + c];
        }
        // w2: 2 x 128 = 128 float2
        if (t < 128) {
            int r = t >> 6, c = (t & 63) * 2;
            *(float2*)&w2s[r][c] = *(const float2*)&W2[r * H + hb + c];
        }
        __syncthreads();

#pragma unroll 16
        for (int hp = 0; hp < P_HC / 2; hp++) {
            ull a0 = *(const ull*)&as[tx][hp * 2];
            ull a1 = *(const ull*)&as[tx + 16][hp * 2];
            ull b0 = *(const ull*)&bs[ty][hp * 2];
            ull w0 = *(const ull*)&w2s[0][hp * 2];
            ull w1 = *(const ull*)&w2s[1][hp * 2];

            ull t0 = tanh2(fadd2(a0, b0));
            ull t1 = tanh2(fadd2(a1, b0));

            acc[0][0] = ffma2(t0, w0, acc[0][0]);
            acc[0][1] = ffma2(t0, w1, acc[0][1]);
            acc[1][0] = ffma2(t1, w0, acc[1][0]);
            acc[1][1] = ffma2(t1, w1, acc[1][1]);
        }
        __syncthreads();
    }

    const int i = iblk + ty;
#pragma unroll
    for (int jv = 0; jv < 2; jv++) {
        const int j = jblk + tx + jv * 16;
        float2 s0 = u2f2(acc[jv][0]);
        float2 s1 = u2f2(acc[jv][1]);
        float2 o;
        o.x = s0.x + s0.y;
        o.y = s1.x + s1.y;
        *(float2*)&g_f[(i * L + j) * 2] = o;
    }
}

// ============================================================
// Kernel 3: out[i,j,c] = 0.5*(f[i,j,c] + f[j,i,c]) + b2[c]
// ============================================================
__global__ __launch_bounds__(256) void k3_sym(const float* __restrict__ b2,
                                              float* __restrict__ out) {
    const int idx = blockIdx.x * 256 + threadIdx.x;
    const int i = idx >> 9;
    const int j = idx & (L - 1);
    const float2 fij = *(const float2*)&g_f[idx * 2];
    const float2 fji = *(const float2*)&g_f[((j << 9) | i) * 2];
    float2 r;
    r.x = (fij.x + fji.x) * 0.5f + b2[0];
    r.y = (fij.y + fji.y) * 0.5f + b2[1];
    *(float2*)&out[idx * 2] = r;
}

extern "C" void kernel_launch(void* const* d_in, const int* in_sizes, int n_in,
                              void* d_out, int out_size) {
    const float* x  = (const float*)d_in[0];
    const float* W1 = (const float*)d_in[1];
    const float* b1 = (const float*)d_in[2];
    const float* W2 = (const float*)d_in[3];
    const float* b2 = (const float*)d_in[4];
    float* out = (float*)d_out;

    k1_mma<<<dim3(H / G_BN, L / G_BM), 256>>>(x, W1, b1);
    k2_pair<<<dim3(L / P_TJ, L / P_TI), 256>>>(W2);
    k3_sym<<<(L * L) / 256, 256>>>(b2, out);
}